// round 2
// baseline (speedup 1.0000x reference)
#include <cuda_runtime.h>
#include <math.h>

// ---------------------------------------------------------------------------
// CDConv: offset-conv(3x3,128->256)+tanh -> depthwise(3x3) -> grid_sample ->
//         pointwise(1x1,128->256)
// Shapes: B=16, C=128, H=W=112, OUTC=256
// ---------------------------------------------------------------------------

#define BB   16
#define CC   128
#define HH   112
#define WW   112
#define HW   12544           // 112*112
#define MOFF 256             // 2*C  (offset conv output channels)
#define MOUT 256             // OUTC

// scratch (device globals; no runtime allocation allowed)
__device__ float g_offset[BB * MOFF * HW];   // [B, 2C, H, W]  ~205 MB
__device__ float g_dw[BB * CC * HW];         // depthwise out  ~103 MB
__device__ float g_samp[BB * CC * HW];       // sampled        ~103 MB

// ---------------------------------------------------------------------------
// Tiled SGEMM:  C[m,n] = sum_k A[m,k] * B[k,n]
//   M = 256 (template MM), N = B*HW = 200704, K template.
//   IM2COL=true : B[k,n] = im2col of x for 3x3 pad-1 conv (k -> cin,kh,kw)
//   IM2COL=false: B[k,n] = Bsrc[(b*K + k)*HW + rem]   (1x1 conv over sampled)
//   DO_TANH     : epilogue v = tanhf(acc + bias[m]); else v = acc
// Output layout: Cdst[((b*MM + m)*HW) + rem]
// BN=128 divides HW (12544 = 98*128) so each block sits in one image.
// ---------------------------------------------------------------------------

constexpr int BM = 128, BN = 128, BK = 8, TM = 8, TN = 8;

template <int K, int MM, bool IM2COL, bool DO_TANH>
__global__ __launch_bounds__(256)
void sgemm_conv(const float* __restrict__ A,
                const float* __restrict__ Bsrc,
                const float* __restrict__ bias,
                float* __restrict__ Cdst)
{
    __shared__ float As[BK][BM];
    __shared__ float Bs[BK][BN];

    const int tid  = threadIdx.x;
    const int tRow = tid >> 4;        // 0..15
    const int tCol = tid & 15;        // 0..15

    const int nBase   = blockIdx.x * BN;
    const int b_img   = nBase / HW;   // constant within block
    const int remBase = nBase % HW;
    const int mBase   = blockIdx.y * BM;

    // global-load thread mapping
    const int aRow = tid >> 1;              // 0..127
    const int aCol = (tid & 1) * 4;         // 0 or 4
    const int bRow = tid >> 5;              // 0..7
    const int bCol = (tid & 31) * 4;        // 0..124

    float acc[TM][TN];
#pragma unroll
    for (int i = 0; i < TM; i++)
#pragma unroll
        for (int j = 0; j < TN; j++) acc[i][j] = 0.f;

    float regM[TM], regN[TN];

    for (int k0 = 0; k0 < K; k0 += BK) {
        // ---- load A tile (transposed into As) ----
        float4 a4 = *reinterpret_cast<const float4*>(
            A + (mBase + aRow) * K + k0 + aCol);
        As[aCol + 0][aRow] = a4.x;
        As[aCol + 1][aRow] = a4.y;
        As[aCol + 2][aRow] = a4.z;
        As[aCol + 3][aRow] = a4.w;

        // ---- load B tile ----
        const int k = k0 + bRow;
        if (IM2COL) {
            const int cin = k / 9;
            const int r   = k - cin * 9;
            const int kh  = r / 3 - 1;
            const int kw  = r - (r / 3) * 3 - 1;
            const float* xp = Bsrc + (b_img * CC + cin) * HW;
#pragma unroll
            for (int i = 0; i < 4; i++) {
                const int rem = remBase + bCol + i;
                const int h   = rem / WW;
                const int w   = rem - h * WW;
                const int ih  = h + kh;
                const int iw  = w + kw;
                float v = 0.f;
                if ((unsigned)ih < (unsigned)HH && (unsigned)iw < (unsigned)WW)
                    v = __ldg(xp + ih * WW + iw);
                Bs[bRow][bCol + i] = v;
            }
        } else {
            const float4 b4 = *reinterpret_cast<const float4*>(
                Bsrc + (b_img * K + k) * HW + remBase + bCol);
            Bs[bRow][bCol + 0] = b4.x;
            Bs[bRow][bCol + 1] = b4.y;
            Bs[bRow][bCol + 2] = b4.z;
            Bs[bRow][bCol + 3] = b4.w;
        }
        __syncthreads();

        // ---- compute ----
#pragma unroll
        for (int kk = 0; kk < BK; kk++) {
#pragma unroll
            for (int i = 0; i < TM; i += 4) {
                float4 m4 = *reinterpret_cast<const float4*>(&As[kk][tRow * TM + i]);
                regM[i + 0] = m4.x; regM[i + 1] = m4.y;
                regM[i + 2] = m4.z; regM[i + 3] = m4.w;
            }
#pragma unroll
            for (int j = 0; j < TN; j += 4) {
                float4 n4 = *reinterpret_cast<const float4*>(&Bs[kk][tCol * TN + j]);
                regN[j + 0] = n4.x; regN[j + 1] = n4.y;
                regN[j + 2] = n4.z; regN[j + 3] = n4.w;
            }
#pragma unroll
            for (int i = 0; i < TM; i++)
#pragma unroll
                for (int j = 0; j < TN; j++)
                    acc[i][j] = fmaf(regM[i], regN[j], acc[i][j]);
        }
        __syncthreads();
    }

    // ---- epilogue ----
#pragma unroll
    for (int i = 0; i < TM; i++) {
        const int m = mBase + tRow * TM + i;
        float bi = 0.f;
        if (DO_TANH) bi = bias[m];
        float* cp = Cdst + (b_img * MM + m) * HW + remBase + tCol * TN;
        float out[TN];
#pragma unroll
        for (int j = 0; j < TN; j++) {
            float v = acc[i][j] + bi;
            if (DO_TANH) v = tanhf(v);
            out[j] = v;
        }
        *reinterpret_cast<float4*>(cp)     = make_float4(out[0], out[1], out[2], out[3]);
        *reinterpret_cast<float4*>(cp + 4) = make_float4(out[4], out[5], out[6], out[7]);
    }
}

// ---------------------------------------------------------------------------
// Depthwise 3x3, pad 1, groups=C, no bias.
// ---------------------------------------------------------------------------
__global__ __launch_bounds__(256)
void depthwise_k(const float* __restrict__ x,
                 const float* __restrict__ wgt,
                 float* __restrict__ out)
{
    const int idx = blockIdx.x * blockDim.x + threadIdx.x;
    if (idx >= BB * CC * HW) return;
    const int rem = idx % HW;
    const int bc  = idx / HW;
    const int c   = bc % CC;
    const int h   = rem / WW;
    const int w   = rem - h * WW;

    const float* wp = wgt + c * 9;
    const float* xp = x + bc * HW;

    float accv = 0.f;
#pragma unroll
    for (int kh = 0; kh < 3; kh++) {
        const int ih = h + kh - 1;
        if ((unsigned)ih >= (unsigned)HH) continue;
#pragma unroll
        for (int kw = 0; kw < 3; kw++) {
            const int iw = w + kw - 1;
            if ((unsigned)iw >= (unsigned)WW) continue;
            accv = fmaf(__ldg(xp + ih * WW + iw), __ldg(wp + kh * 3 + kw), accv);
        }
    }
    out[idx] = accv;
}

// ---------------------------------------------------------------------------
// Grid sample (bilinear, zeros padding, align_corners=False), with the
// reference's channel interleave:
//   x-coord for channel c = clip(base(2c)   + offset[b,2c  ,h,w], -1, 1)
//   y-coord for channel c = clip(base(2c+1) + offset[b,2c+1,h,w], -1, 1)
//   base(j) = gX(w) if j < C else gY(h)
// ---------------------------------------------------------------------------
__global__ __launch_bounds__(256)
void gridsample_k(const float* __restrict__ off,
                  const float* __restrict__ src,
                  float* __restrict__ dst)
{
    const int idx = blockIdx.x * blockDim.x + threadIdx.x;
    if (idx >= BB * CC * HW) return;
    const int rem = idx % HW;
    const int bc  = idx / HW;
    const int b   = bc / CC;
    const int c   = bc % CC;
    const int h   = rem / WW;
    const int w   = rem - h * WW;

    const float gx = -1.f + 2.f * (float)w / (float)(WW - 1);
    const float gy = -1.f + 2.f * (float)h / (float)(HH - 1);

    const int jx = 2 * c;
    const int jy = 2 * c + 1;
    const float basex = (jx < CC) ? gx : gy;
    const float basey = (jy < CC) ? gx : gy;

    const float offx = __ldg(off + (b * MOFF + jx) * HW + rem);
    const float offy = __ldg(off + (b * MOFF + jy) * HW + rem);

    float sx = fminf(fmaxf(basex + offx, -1.f), 1.f);
    float sy = fminf(fmaxf(basey + offy, -1.f), 1.f);

    // align_corners=False mapping
    const float ix = (sx + 1.f) * ((float)WW * 0.5f) - 0.5f;
    const float iy = (sy + 1.f) * ((float)HH * 0.5f) - 0.5f;

    const float x0f = floorf(ix);
    const float y0f = floorf(iy);
    const float wx  = ix - x0f;
    const float wy  = iy - y0f;
    const int x0 = (int)x0f;
    const int y0 = (int)y0f;

    const float* ch = src + bc * HW;

    auto gather = [&](int yi, int xi) -> float {
        if ((unsigned)yi < (unsigned)HH && (unsigned)xi < (unsigned)WW)
            return __ldg(ch + yi * WW + xi);
        return 0.f;
    };

    const float v00 = gather(y0,     x0);
    const float v01 = gather(y0,     x0 + 1);
    const float v10 = gather(y0 + 1, x0);
    const float v11 = gather(y0 + 1, x0 + 1);

    dst[idx] = v00 * (1.f - wx) * (1.f - wy)
             + v01 * wx         * (1.f - wy)
             + v10 * (1.f - wx) * wy
             + v11 * wx         * wy;
}

// ---------------------------------------------------------------------------
// launch
// ---------------------------------------------------------------------------
extern "C" void kernel_launch(void* const* d_in, const int* in_sizes, int n_in,
                              void* d_out, int out_size)
{
    const float* x        = (const float*)d_in[0];  // [16,128,112,112]
    const float* depth_w  = (const float*)d_in[1];  // [128,1,3,3]
    const float* point_w  = (const float*)d_in[2];  // [256,128,1,1]
    const float* offset_w = (const float*)d_in[3];  // [256,128,3,3]
    const float* offset_b = (const float*)d_in[4];  // [256]
    float* out = (float*)d_out;                     // [16,256,112,112]

    float* offset_p; cudaGetSymbolAddress((void**)&offset_p, g_offset);
    float* dw_p;     cudaGetSymbolAddress((void**)&dw_p,     g_dw);
    float* samp_p;   cudaGetSymbolAddress((void**)&samp_p,   g_samp);

    const int Ntot = BB * HW;                 // 200704
    dim3 gemmGrid(Ntot / BN, MOFF / BM);      // (1568, 2)

    // 1) offset = tanh(conv3x3(x, offset_w) + b)
    sgemm_conv<1152, MOFF, true, true><<<gemmGrid, 256>>>(
        offset_w, x, offset_b, offset_p);

    // 2) depthwise conv
    {
        const int total = BB * CC * HW;
        depthwise_k<<<(total + 255) / 256, 256>>>(x, depth_w, dw_p);
    }

    // 3) grid sample
    {
        const int total = BB * CC * HW;
        gridsample_k<<<(total + 255) / 256, 256>>>(offset_p, dw_p, samp_p);
    }

    // 4) pointwise 1x1 conv -> d_out
    sgemm_conv<128, MOUT, false, false><<<gemmGrid, 256>>>(
        point_w, samp_p, nullptr, out);
}

// round 4
// speedup vs baseline: 1.0561x; 1.0561x over previous
#include <cuda_runtime.h>
#include <cstdint>
#include <math.h>

// ---------------------------------------------------------------------------
// CDConv: offset-conv(3x3,128->256)+tanh -> depthwise(3x3) -> grid_sample ->
//         pointwise(1x1,128->256)
// B=16, C=128, H=W=112, OUTC=256
// fp32 GEMMs using packed fma.rn.f32x2 (SASS FFMA2, 2x FFMA throughput).
// ---------------------------------------------------------------------------

#define BB   16
#define CC   128
#define HH   112
#define WW   112
#define HW   12544
#define MOFF 256
#define MOUT 256

__device__ float g_offset[BB * MOFF * HW];
__device__ float g_dw[BB * CC * HW];
__device__ float g_samp[BB * CC * HW];

// -------------------- packed f32x2 helpers ---------------------------------
typedef unsigned long long ull;

__device__ __forceinline__ ull pack_dup(float v) {
    ull r;
    asm("mov.b64 %0, {%1, %1};" : "=l"(r) : "f"(v));
    return r;
}
__device__ __forceinline__ void unpack2(float& lo, float& hi, ull v) {
    asm("mov.b64 {%0, %1}, %2;" : "=f"(lo), "=f"(hi) : "l"(v));
}
__device__ __forceinline__ ull fma2(ull a, ull b, ull c) {
    ull d;
    asm("fma.rn.f32x2 %0, %1, %2, %3;" : "=l"(d) : "l"(a), "l"(b), "l"(c));
    return d;
}

// ---------------------------------------------------------------------------
// Tiled GEMM with f32x2 microkernel.
//   C[m,n] = sum_k A[m,k] * B[k,n]
//   IM2COL=true : B[k,n] = im2col(x) for 3x3 pad-1 conv (k -> cin,kh,kw)
//   IM2COL=false: B[k,n] = Bsrc[(b*K + k)*HW + rem]
//   DO_TANH     : v = tanhf(acc + bias[m])
// Output: Cdst[((b*MM + m)*HW) + rem]. BN=128 divides HW.
// ---------------------------------------------------------------------------
constexpr int BM = 128, BN = 128, BK = 16, TM = 8, TN = 8;

template <int K, int MM, bool IM2COL, bool DO_TANH>
__global__ __launch_bounds__(256)
void sgemm_conv(const float* __restrict__ A,
                const float* __restrict__ Bsrc,
                const float* __restrict__ bias,
                float* __restrict__ Cdst)
{
    __shared__ float As[BK][BM];
    __shared__ float Bs[BK][BN];

    const int tid  = threadIdx.x;
    const int tRow = tid >> 4;        // 0..15
    const int tCol = tid & 15;        // 0..15

    const int nBase   = blockIdx.x * BN;
    const int b_img   = nBase / HW;
    const int remBase = nBase % HW;
    const int mBase   = blockIdx.y * BM;

    // global-load thread mapping (BK=16)
    const int aRow = tid >> 1;               // 0..127
    const int aCol = (tid & 1) * 8;          // 0 or 8
    const int bRow = tid >> 4;               // 0..15
    const int bCol = (tid & 15) * 8;         // 0..120

    ull acc2[TM][TN / 2];
#pragma unroll
    for (int i = 0; i < TM; i++)
#pragma unroll
        for (int j = 0; j < TN / 2; j++) acc2[i][j] = 0ull;

    for (int k0 = 0; k0 < K; k0 += BK) {
        // ---- load A tile (transpose into As) ----
        {
            const float* ap = A + (mBase + aRow) * K + k0 + aCol;
            float4 a0 = *reinterpret_cast<const float4*>(ap);
            float4 a1 = *reinterpret_cast<const float4*>(ap + 4);
            As[aCol + 0][aRow] = a0.x;  As[aCol + 1][aRow] = a0.y;
            As[aCol + 2][aRow] = a0.z;  As[aCol + 3][aRow] = a0.w;
            As[aCol + 4][aRow] = a1.x;  As[aCol + 5][aRow] = a1.y;
            As[aCol + 6][aRow] = a1.z;  As[aCol + 7][aRow] = a1.w;
        }
        // ---- load B tile ----
        {
            const int k = k0 + bRow;
            if (IM2COL) {
                const int cin = k / 9;
                const int r   = k - cin * 9;
                const int kh  = r / 3 - 1;
                const int kw  = r - (r / 3) * 3 - 1;
                const float* xp = Bsrc + ((size_t)b_img * CC + cin) * HW;
#pragma unroll
                for (int i = 0; i < 8; i++) {
                    const int rem = remBase + bCol + i;
                    const int h   = rem / WW;
                    const int w   = rem - h * WW;
                    const int ih  = h + kh;
                    const int iw  = w + kw;
                    float v = 0.f;
                    if ((unsigned)ih < (unsigned)HH && (unsigned)iw < (unsigned)WW)
                        v = __ldg(xp + ih * WW + iw);
                    Bs[bRow][bCol + i] = v;
                }
            } else {
                const float* bp = Bsrc + ((size_t)b_img * K + k) * HW + remBase + bCol;
                float4 b0 = *reinterpret_cast<const float4*>(bp);
                float4 b1 = *reinterpret_cast<const float4*>(bp + 4);
                *reinterpret_cast<float4*>(&Bs[bRow][bCol])     = b0;
                *reinterpret_cast<float4*>(&Bs[bRow][bCol + 4]) = b1;
            }
        }
        __syncthreads();

        // ---- compute: 16 k-steps, 8x8 per thread via 32 FFMA2 per step ----
#pragma unroll
        for (int kk = 0; kk < BK; kk++) {
            ull regM2[TM];
#pragma unroll
            for (int i = 0; i < TM; i += 4) {
                float4 m4 = *reinterpret_cast<const float4*>(&As[kk][tRow * TM + i]);
                regM2[i + 0] = pack_dup(m4.x);
                regM2[i + 1] = pack_dup(m4.y);
                regM2[i + 2] = pack_dup(m4.z);
                regM2[i + 3] = pack_dup(m4.w);
            }
            ull regN2[TN / 2];
            {
                ulonglong2 n0 = *reinterpret_cast<const ulonglong2*>(&Bs[kk][tCol * TN]);
                ulonglong2 n1 = *reinterpret_cast<const ulonglong2*>(&Bs[kk][tCol * TN + 4]);
                regN2[0] = n0.x; regN2[1] = n0.y;
                regN2[2] = n1.x; regN2[3] = n1.y;
            }
#pragma unroll
            for (int i = 0; i < TM; i++)
#pragma unroll
                for (int j = 0; j < TN / 2; j++)
                    acc2[i][j] = fma2(regM2[i], regN2[j], acc2[i][j]);
        }
        __syncthreads();
    }

    // ---- epilogue ----
#pragma unroll
    for (int i = 0; i < TM; i++) {
        const int m = mBase + tRow * TM + i;
        float bi = 0.f;
        if (DO_TANH) bi = bias[m];
        float* cp = Cdst + ((size_t)b_img * MM + m) * HW + remBase + tCol * TN;
        float out[TN];
#pragma unroll
        for (int j = 0; j < TN / 2; j++) {
            float lo, hi;
            unpack2(lo, hi, acc2[i][j]);
            float v0 = lo + bi, v1 = hi + bi;
            if (DO_TANH) { v0 = tanhf(v0); v1 = tanhf(v1); }
            out[2 * j] = v0; out[2 * j + 1] = v1;
        }
        *reinterpret_cast<float4*>(cp)     = make_float4(out[0], out[1], out[2], out[3]);
        *reinterpret_cast<float4*>(cp + 4) = make_float4(out[4], out[5], out[6], out[7]);
    }
}

// ---------------------------------------------------------------------------
// Depthwise 3x3, pad 1, groups=C, no bias.
// ---------------------------------------------------------------------------
__global__ __launch_bounds__(256)
void depthwise_k(const float* __restrict__ x,
                 const float* __restrict__ wgt,
                 float* __restrict__ out)
{
    const int idx = blockIdx.x * blockDim.x + threadIdx.x;
    if (idx >= BB * CC * HW) return;
    const int rem = idx % HW;
    const int bc  = idx / HW;
    const int c   = bc % CC;
    const int h   = rem / WW;
    const int w   = rem - h * WW;

    const float* wp = wgt + c * 9;
    const float* xp = x + (size_t)bc * HW;

    float accv = 0.f;
#pragma unroll
    for (int kh = 0; kh < 3; kh++) {
        const int ih = h + kh - 1;
        if ((unsigned)ih >= (unsigned)HH) continue;
#pragma unroll
        for (int kw = 0; kw < 3; kw++) {
            const int iw = w + kw - 1;
            if ((unsigned)iw >= (unsigned)WW) continue;
            accv = fmaf(__ldg(xp + ih * WW + iw), __ldg(wp + kh * 3 + kw), accv);
        }
    }
    out[idx] = accv;
}

// ---------------------------------------------------------------------------
// Grid sample (bilinear, zeros pad, align_corners=False) with the reference's
// channel interleave.
// ---------------------------------------------------------------------------
__global__ __launch_bounds__(256)
void gridsample_k(const float* __restrict__ off,
                  const float* __restrict__ src,
                  float* __restrict__ dst)
{
    const int idx = blockIdx.x * blockDim.x + threadIdx.x;
    if (idx >= BB * CC * HW) return;
    const int rem = idx % HW;
    const int bc  = idx / HW;
    const int b   = bc / CC;
    const int c   = bc % CC;
    const int h   = rem / WW;
    const int w   = rem - h * WW;

    const float gx = -1.f + 2.f * (float)w / (float)(WW - 1);
    const float gy = -1.f + 2.f * (float)h / (float)(HH - 1);

    const int jx = 2 * c;
    const int jy = 2 * c + 1;
    const float basex = (jx < CC) ? gx : gy;
    const float basey = (jy < CC) ? gx : gy;

    const float offx = __ldg(off + ((size_t)b * MOFF + jx) * HW + rem);
    const float offy = __ldg(off + ((size_t)b * MOFF + jy) * HW + rem);

    float sx = fminf(fmaxf(basex + offx, -1.f), 1.f);
    float sy = fminf(fmaxf(basey + offy, -1.f), 1.f);

    const float ix = (sx + 1.f) * ((float)WW * 0.5f) - 0.5f;
    const float iy = (sy + 1.f) * ((float)HH * 0.5f) - 0.5f;

    const float x0f = floorf(ix);
    const float y0f = floorf(iy);
    const float wx  = ix - x0f;
    const float wy  = iy - y0f;
    const int x0 = (int)x0f;
    const int y0 = (int)y0f;

    const float* ch = src + (size_t)bc * HW;

    auto gather = [&](int yi, int xi) -> float {
        if ((unsigned)yi < (unsigned)HH && (unsigned)xi < (unsigned)WW)
            return __ldg(ch + yi * WW + xi);
        return 0.f;
    };

    const float v00 = gather(y0,     x0);
    const float v01 = gather(y0,     x0 + 1);
    const float v10 = gather(y0 + 1, x0);
    const float v11 = gather(y0 + 1, x0 + 1);

    dst[idx] = v00 * (1.f - wx) * (1.f - wy)
             + v01 * wx         * (1.f - wy)
             + v10 * (1.f - wx) * wy
             + v11 * wx         * wy;
}

// ---------------------------------------------------------------------------
extern "C" void kernel_launch(void* const* d_in, const int* in_sizes, int n_in,
                              void* d_out, int out_size)
{
    const float* x        = (const float*)d_in[0];
    const float* depth_w  = (const float*)d_in[1];
    const float* point_w  = (const float*)d_in[2];
    const float* offset_w = (const float*)d_in[3];
    const float* offset_b = (const float*)d_in[4];
    float* out = (float*)d_out;

    float* offset_p; cudaGetSymbolAddress((void**)&offset_p, g_offset);
    float* dw_p;     cudaGetSymbolAddress((void**)&dw_p,     g_dw);
    float* samp_p;   cudaGetSymbolAddress((void**)&samp_p,   g_samp);

    const int Ntot = BB * HW;
    dim3 gemmGrid(Ntot / BN, MOFF / BM);

    // 1) offset = tanh(conv3x3(x, offset_w) + b)
    sgemm_conv<1152, MOFF, true, true><<<gemmGrid, 256>>>(
        offset_w, x, offset_b, offset_p);

    // 2) depthwise conv
    {
        const int total = BB * CC * HW;
        depthwise_k<<<(total + 255) / 256, 256>>>(x, depth_w, dw_p);
    }

    // 3) grid sample
    {
        const int total = BB * CC * HW;
        gridsample_k<<<(total + 255) / 256, 256>>>(offset_p, dw_p, samp_p);
    }

    // 4) pointwise 1x1 -> out
    sgemm_conv<128, MOUT, false, false><<<gemmGrid, 256>>>(
        point_w, samp_p, nullptr, out);
}

// round 5
// speedup vs baseline: 1.0725x; 1.0155x over previous
#include <cuda_runtime.h>
#include <cstdint>
#include <math.h>

// ---------------------------------------------------------------------------
// CDConv: offset-conv(3x3,128->256)+tanh -> depthwise(3x3) -> grid_sample ->
//         pointwise(1x1,128->256)
// B=16, C=128, H=W=112, OUTC=256
// GEMMs: f32x2 (FFMA2) microkernel, pre-duplicated A operand, cp.async
// double-buffered pipeline, shift-major im2col.
// ---------------------------------------------------------------------------

#define BB   16
#define CC   128
#define HH   112
#define WW   112
#define HW   12544
#define MOFF 256
#define MOUT 256

__device__ float g_offset[BB * MOFF * HW];
__device__ float g_dw[BB * CC * HW];
__device__ float g_samp[BB * CC * HW];
__device__ float g_Adup_off[1152 * 512];   // [k][2m] duplicated, k = s*128+c
__device__ float g_Adup_pw[128 * 512];     // [k][2m] duplicated

typedef unsigned long long ull;

__device__ __forceinline__ void unpack2(float& lo, float& hi, ull v) {
    asm("mov.b64 {%0, %1}, %2;" : "=f"(lo), "=f"(hi) : "l"(v));
}
__device__ __forceinline__ ull fma2(ull a, ull b, ull c) {
    ull d;
    asm("fma.rn.f32x2 %0, %1, %2, %3;" : "=l"(d) : "l"(a), "l"(b), "l"(c));
    return d;
}
__device__ __forceinline__ uint32_t smem_u32(const void* p) {
    uint32_t a;
    asm("{ .reg .u64 t; cvta.to.shared.u64 t, %1; cvt.u32.u64 %0, t; }"
        : "=r"(a) : "l"(p));
    return a;
}
__device__ __forceinline__ void cp16(uint32_t dst, const void* src) {
    asm volatile("cp.async.cg.shared.global [%0], [%1], 16;"
                 :: "r"(dst), "l"(src) : "memory");
}
__device__ __forceinline__ void cp4z(uint32_t dst, const void* src, uint32_t sz) {
    asm volatile("cp.async.ca.shared.global [%0], [%1], 4, %2;"
                 :: "r"(dst), "l"(src), "r"(sz) : "memory");
}
#define CP_COMMIT() asm volatile("cp.async.commit_group;" ::: "memory")
#define CP_WAIT(n)  asm volatile("cp.async.wait_group %0;" :: "n"(n) : "memory")

// ---------------------------------------------------------------------------
// prep: duplicate+reorder weights
// offset: Adup_off[(s*128+c)*512 + 2m(+1)] = ow[m*1152 + c*9 + s]
// ---------------------------------------------------------------------------
__global__ void wprep_off(const float* __restrict__ ow) {
    int idx = blockIdx.x * blockDim.x + threadIdx.x;   // k*256+m
    if (idx >= 1152 * 256) return;
    int m = idx & 255;
    int k = idx >> 8;
    int c = k & 127;
    int s = k >> 7;
    float v = ow[m * 1152 + c * 9 + s];
    g_Adup_off[(size_t)k * 512 + 2 * m]     = v;
    g_Adup_off[(size_t)k * 512 + 2 * m + 1] = v;
}
__global__ void wprep_pw(const float* __restrict__ pw) {
    int idx = blockIdx.x * blockDim.x + threadIdx.x;   // k*256+m
    if (idx >= 128 * 256) return;
    int m = idx & 255;
    int k = idx >> 8;
    float v = pw[m * 128 + k];
    g_Adup_pw[(size_t)k * 512 + 2 * m]     = v;
    g_Adup_pw[(size_t)k * 512 + 2 * m + 1] = v;
}

// ---------------------------------------------------------------------------
// GEMM: C[m,n] = sum_k Adup[k][m] * B[k,n]
//   M tile 128 (of 256), N tile 128 pixels, BK=16, 256 thr, TM=8 x TN=8.
//   IM2COL: B[k,n] from x with k = shift*128+cin (zfill halo)
//   else:   B[k,n] = Bsrc[(b*K+k)*HW + rem]
// smem: As2[2][16][256] (duplicated pairs) + Bs[2][16][128]  = 48KB
// ---------------------------------------------------------------------------
#define BKT 16
#define AS_FLOATS (BKT * 256)     // per buffer
#define BS_FLOATS (BKT * 128)

template <int K, bool IM2COL, bool DO_TANH>
__global__ __launch_bounds__(256, 2)
void gemm2(const float* __restrict__ Adup,
           const float* __restrict__ Bsrc,
           const float* __restrict__ bias,
           float* __restrict__ Cdst)
{
    extern __shared__ float smemf[];
    float* As2 = smemf;                    // [2][BKT][256]
    float* Bsm = smemf + 2 * AS_FLOATS;    // [2][BKT][128]
    const uint32_t sA = smem_u32(As2);
    const uint32_t sB = smem_u32(Bsm);

    const int tid  = threadIdx.x;
    const int tRow = tid >> 4;             // 0..15
    const int tCol = tid & 15;             // 0..15

    const int nBase   = blockIdx.x * 128;
    const int b_img   = nBase / HW;
    const int remBase = nBase % HW;
    const int mBase   = blockIdx.y * 128;

    // load-thread mapping
    const int aRow   = tid >> 4;           // 0..15 (k row)
    const int aCol16 = (tid & 15) * 16;    // duplicated-float offset
    const int bRow   = tid >> 4;           // 0..15 (k row)
    const int bCol   = (tid & 15) * 8;     // pixel offset

    // precompute this thread's 8 pixel coords (constant across tiles)
    int ph[8], pw_[8];
#pragma unroll
    for (int i = 0; i < 8; i++) {
        const int rem = remBase + bCol + i;
        ph[i] = rem / WW;
        pw_[i] = rem - ph[i] * WW;
    }

    constexpr int NT = K / BKT;

    auto load_stage = [&](int t, int buf) {
        // ---- A: 16 floats (4x cp16), contiguous ----
        {
            const float* src = Adup + ((size_t)(t * BKT + aRow)) * 512
                             + mBase * 2 + aCol16;
            const uint32_t dst = sA + (buf * AS_FLOATS + aRow * 256 + aCol16) * 4;
            cp16(dst,      src);
            cp16(dst + 16, src + 4);
            cp16(dst + 32, src + 8);
            cp16(dst + 48, src + 12);
        }
        // ---- B ----
        const uint32_t bdst = sB + (buf * BS_FLOATS + bRow * 128 + bCol) * 4;
        if (IM2COL) {
            const int s   = t >> 3;                 // shift 0..8
            const int dh  = s / 3 - 1;
            const int dw  = s % 3 - 1;
            const int cin = ((t & 7) * BKT) + bRow;
            const float* src = Bsrc + ((size_t)b_img * CC + cin) * HW;
#pragma unroll
            for (int i = 0; i < 8; i++) {
                int ih = ph[i] + dh;
                int iw = pw_[i] + dw;
                const bool ok = ((unsigned)ih < (unsigned)HH) &
                                ((unsigned)iw < (unsigned)WW);
                ih = ih < 0 ? 0 : (ih > HH - 1 ? HH - 1 : ih);
                iw = iw < 0 ? 0 : (iw > WW - 1 ? WW - 1 : iw);
                cp4z(bdst + i * 4, src + ih * WW + iw, ok ? 4u : 0u);
            }
        } else {
            const int k = t * BKT + bRow;
            const float* src = Bsrc + ((size_t)b_img * K + k) * HW + remBase + bCol;
            cp16(bdst,      src);
            cp16(bdst + 16, src + 4);
        }
    };

    ull acc2[8][4];
#pragma unroll
    for (int i = 0; i < 8; i++)
#pragma unroll
        for (int j = 0; j < 4; j++) acc2[i][j] = 0ull;

    load_stage(0, 0);
    CP_COMMIT();

    for (int t = 0; t < NT; t++) {
        const int buf = t & 1;
        if (t + 1 < NT) {
            load_stage(t + 1, buf ^ 1);
            CP_COMMIT();
            CP_WAIT(1);
        } else {
            CP_WAIT(0);
        }
        __syncthreads();

        const float* abase = As2 + buf * AS_FLOATS + tRow * 16;
        const float* bbase = Bsm + buf * BS_FLOATS + tCol * 8;
#pragma unroll
        for (int kk = 0; kk < BKT; kk++) {
            ull regM2[8];
            {
                const ulonglong2* ap =
                    reinterpret_cast<const ulonglong2*>(abase + kk * 256);
                ulonglong2 q0 = ap[0];
                ulonglong2 q1 = ap[1];
                ulonglong2 q2 = ap[2];
                ulonglong2 q3 = ap[3];
                regM2[0] = q0.x; regM2[1] = q0.y;
                regM2[2] = q1.x; regM2[3] = q1.y;
                regM2[4] = q2.x; regM2[5] = q2.y;
                regM2[6] = q3.x; regM2[7] = q3.y;
            }
            ull regN2[4];
            {
                const ulonglong2* bp =
                    reinterpret_cast<const ulonglong2*>(bbase + kk * 128);
                ulonglong2 n0 = bp[0];
                ulonglong2 n1 = bp[1];
                regN2[0] = n0.x; regN2[1] = n0.y;
                regN2[2] = n1.x; regN2[3] = n1.y;
            }
#pragma unroll
            for (int i = 0; i < 8; i++)
#pragma unroll
                for (int j = 0; j < 4; j++)
                    acc2[i][j] = fma2(regM2[i], regN2[j], acc2[i][j]);
        }
        __syncthreads();
    }

    // ---- epilogue ----
#pragma unroll
    for (int i = 0; i < 8; i++) {
        const int m = mBase + tRow * 8 + i;
        float bi = 0.f;
        if (DO_TANH) bi = bias[m];
        float* cp = Cdst + ((size_t)b_img * 256 + m) * HW + remBase + tCol * 8;
        float out[8];
#pragma unroll
        for (int j = 0; j < 4; j++) {
            float lo, hi;
            unpack2(lo, hi, acc2[i][j]);
            float v0 = lo + bi, v1 = hi + bi;
            if (DO_TANH) { v0 = tanhf(v0); v1 = tanhf(v1); }
            out[2 * j] = v0; out[2 * j + 1] = v1;
        }
        *reinterpret_cast<float4*>(cp)     = make_float4(out[0], out[1], out[2], out[3]);
        *reinterpret_cast<float4*>(cp + 4) = make_float4(out[4], out[5], out[6], out[7]);
    }
}

// ---------------------------------------------------------------------------
// Depthwise 3x3, pad 1, groups=C, no bias.
// ---------------------------------------------------------------------------
__global__ __launch_bounds__(256)
void depthwise_k(const float* __restrict__ x,
                 const float* __restrict__ wgt,
                 float* __restrict__ out)
{
    const int idx = blockIdx.x * blockDim.x + threadIdx.x;
    if (idx >= BB * CC * HW) return;
    const int rem = idx % HW;
    const int bc  = idx / HW;
    const int c   = bc % CC;
    const int h   = rem / WW;
    const int w   = rem - h * WW;

    const float* wp = wgt + c * 9;
    const float* xp = x + (size_t)bc * HW;

    float accv = 0.f;
#pragma unroll
    for (int kh = 0; kh < 3; kh++) {
        const int ih = h + kh - 1;
        if ((unsigned)ih >= (unsigned)HH) continue;
#pragma unroll
        for (int kw = 0; kw < 3; kw++) {
            const int iw = w + kw - 1;
            if ((unsigned)iw >= (unsigned)WW) continue;
            accv = fmaf(__ldg(xp + ih * WW + iw), __ldg(wp + kh * 3 + kw), accv);
        }
    }
    out[idx] = accv;
}

// ---------------------------------------------------------------------------
// Grid sample (bilinear, zeros pad, align_corners=False), channel-interleaved
// grid exactly as the reference builds it.
// ---------------------------------------------------------------------------
__global__ __launch_bounds__(256)
void gridsample_k(const float* __restrict__ off,
                  const float* __restrict__ src,
                  float* __restrict__ dst)
{
    const int idx = blockIdx.x * blockDim.x + threadIdx.x;
    if (idx >= BB * CC * HW) return;
    const int rem = idx % HW;
    const int bc  = idx / HW;
    const int b   = bc / CC;
    const int c   = bc % CC;
    const int h   = rem / WW;
    const int w   = rem - h * WW;

    const float gx = -1.f + 2.f * (float)w / (float)(WW - 1);
    const float gy = -1.f + 2.f * (float)h / (float)(HH - 1);

    const int jx = 2 * c;
    const int jy = 2 * c + 1;
    const float basex = (jx < CC) ? gx : gy;
    const float basey = (jy < CC) ? gx : gy;

    const float offx = __ldg(off + ((size_t)b * MOFF + jx) * HW + rem);
    const float offy = __ldg(off + ((size_t)b * MOFF + jy) * HW + rem);

    float sx = fminf(fmaxf(basex + offx, -1.f), 1.f);
    float sy = fminf(fmaxf(basey + offy, -1.f), 1.f);

    const float ix = (sx + 1.f) * ((float)WW * 0.5f) - 0.5f;
    const float iy = (sy + 1.f) * ((float)HH * 0.5f) - 0.5f;

    const float x0f = floorf(ix);
    const float y0f = floorf(iy);
    const float wx  = ix - x0f;
    const float wy  = iy - y0f;
    const int x0 = (int)x0f;
    const int y0 = (int)y0f;

    const float* ch = src + (size_t)bc * HW;

    auto gather = [&](int yi, int xi) -> float {
        if ((unsigned)yi < (unsigned)HH && (unsigned)xi < (unsigned)WW)
            return __ldg(ch + yi * WW + xi);
        return 0.f;
    };

    const float v00 = gather(y0,     x0);
    const float v01 = gather(y0,     x0 + 1);
    const float v10 = gather(y0 + 1, x0);
    const float v11 = gather(y0 + 1, x0 + 1);

    dst[idx] = v00 * (1.f - wx) * (1.f - wy)
             + v01 * wx         * (1.f - wy)
             + v10 * (1.f - wx) * wy
             + v11 * wx         * wy;
}

// ---------------------------------------------------------------------------
extern "C" void kernel_launch(void* const* d_in, const int* in_sizes, int n_in,
                              void* d_out, int out_size)
{
    const float* x        = (const float*)d_in[0];
    const float* depth_w  = (const float*)d_in[1];
    const float* point_w  = (const float*)d_in[2];
    const float* offset_w = (const float*)d_in[3];
    const float* offset_b = (const float*)d_in[4];
    float* out = (float*)d_out;

    float* offset_p; cudaGetSymbolAddress((void**)&offset_p, g_offset);
    float* dw_p;     cudaGetSymbolAddress((void**)&dw_p,     g_dw);
    float* samp_p;   cudaGetSymbolAddress((void**)&samp_p,   g_samp);
    float* adoff_p;  cudaGetSymbolAddress((void**)&adoff_p,  g_Adup_off);
    float* adpw_p;   cudaGetSymbolAddress((void**)&adpw_p,   g_Adup_pw);

    const int SMEM = (2 * AS_FLOATS + 2 * BS_FLOATS) * 4;   // 49152
    cudaFuncSetAttribute(gemm2<1152, true, true>,
                         cudaFuncAttributeMaxDynamicSharedMemorySize, SMEM);
    cudaFuncSetAttribute(gemm2<128, false, false>,
                         cudaFuncAttributeMaxDynamicSharedMemorySize, SMEM);

    // 0) weight prep (duplicate + reorder)
    wprep_off<<<(1152 * 256 + 255) / 256, 256>>>(offset_w);
    wprep_pw<<<(128 * 256 + 255) / 256, 256>>>(point_w);

    const int Ntot = BB * HW;
    dim3 gemmGrid(Ntot / 128, 2);

    // 1) offset = tanh(conv3x3(x, offset_w) + b)
    gemm2<1152, true, true><<<gemmGrid, 256, SMEM>>>(
        adoff_p, x, offset_b, offset_p);

    // 2) depthwise conv
    {
        const int total = BB * CC * HW;
        depthwise_k<<<(total + 255) / 256, 256>>>(x, depth_w, dw_p);
    }

    // 3) grid sample
    {
        const int total = BB * CC * HW;
        gridsample_k<<<(total + 255) / 256, 256>>>(offset_p, dw_p, samp_p);
    }

    // 4) pointwise 1x1 -> out
    gemm2<128, false, false><<<gemmGrid, 256, SMEM>>>(
        adpw_p, samp_p, nullptr, out);
}

// round 6
// speedup vs baseline: 1.5548x; 1.4496x over previous
#include <cuda_runtime.h>
#include <cuda_bf16.h>
#include <cstdint>
#include <math.h>

// ---------------------------------------------------------------------------
// CDConv: offset-conv(3x3,128->256, bf16-split mma.sync)+tanh -> depthwise ->
//         grid_sample -> pointwise(1x1,128->256, FFMA2)
// B=16, C=128, H=W=112, OUTC=256
// ---------------------------------------------------------------------------

#define BB   16
#define CC   128
#define HH   112
#define WW   112
#define HW   12544
#define MOFF 256
#define MOUT 256
#define NSTG 36               // K=1152 / 32

__device__ float    g_offset[BB * MOFF * HW];
__device__ float    g_dw[BB * CC * HW];
__device__ float    g_samp[BB * CC * HW];
__device__ uint32_t g_xpk[BB * CC * HW];                  // {bf16 hi | bf16 lo<<16}
__device__ unsigned short g_Aoffbf[NSTG * 2 * 2 * 128 * 32]; // [t][mh][split][m][k]
__device__ float    g_Adup_pw[128 * 512];                 // pointwise FFMA2 weights

typedef unsigned long long ull;

// ======================= helpers ==========================================
__device__ __forceinline__ uint32_t smem_u32(const void* p) {
    uint32_t a;
    asm("{ .reg .u64 t; cvta.to.shared.u64 t, %1; cvt.u32.u64 %0, t; }"
        : "=r"(a) : "l"(p));
    return a;
}
__device__ __forceinline__ void cp16(uint32_t dst, const void* src) {
    asm volatile("cp.async.cg.shared.global [%0], [%1], 16;"
                 :: "r"(dst), "l"(src) : "memory");
}
__device__ __forceinline__ void cp16s(uint32_t dst, const void* src) {
    asm volatile("cp.async.ca.shared.global [%0], [%1], 16;"
                 :: "r"(dst), "l"(src) : "memory");
}
#define CP_COMMIT() asm volatile("cp.async.commit_group;" ::: "memory")
#define CP_WAIT0()  asm volatile("cp.async.wait_group 0;" ::: "memory")

__device__ __forceinline__ uint32_t prmt(uint32_t a, uint32_t b, uint32_t sel) {
    uint32_t d;
    asm("prmt.b32 %0, %1, %2, %3;" : "=r"(d) : "r"(a), "r"(b), "r"(sel));
    return d;
}
__device__ __forceinline__ void sts128(uint32_t a, uint32_t x, uint32_t y,
                                       uint32_t z, uint32_t w) {
    asm volatile("st.shared.v4.b32 [%0], {%1,%2,%3,%4};"
                 :: "r"(a), "r"(x), "r"(y), "r"(z), "r"(w) : "memory");
}
__device__ __forceinline__ void ldsm_x4(uint32_t* r, uint32_t addr) {
    asm volatile("ldmatrix.sync.aligned.m8n8.x4.shared.b16 {%0,%1,%2,%3}, [%4];"
                 : "=r"(r[0]), "=r"(r[1]), "=r"(r[2]), "=r"(r[3]) : "r"(addr));
}
__device__ __forceinline__ void ldsm_x2t(uint32_t* r, uint32_t addr) {
    asm volatile("ldmatrix.sync.aligned.m8n8.x2.trans.shared.b16 {%0,%1}, [%2];"
                 : "=r"(r[0]), "=r"(r[1]) : "r"(addr));
}
__device__ __forceinline__ void mma_bf16(float* c, const uint32_t* a, const uint32_t* b) {
    asm volatile(
        "mma.sync.aligned.m16n8k16.row.col.f32.bf16.bf16.f32 "
        "{%0,%1,%2,%3}, {%4,%5,%6,%7}, {%8,%9}, {%0,%1,%2,%3};"
        : "+f"(c[0]), "+f"(c[1]), "+f"(c[2]), "+f"(c[3])
        : "r"(a[0]), "r"(a[1]), "r"(a[2]), "r"(a[3]), "r"(b[0]), "r"(b[1]));
}

__device__ __forceinline__ void bf_split(float v, unsigned short& hu, unsigned short& lu) {
    __nv_bfloat16 h = __float2bfloat16(v);
    float hf = __bfloat162float(h);
    __nv_bfloat16 l = __float2bfloat16(v - hf);
    hu = reinterpret_cast<unsigned short&>(h);
    lu = reinterpret_cast<unsigned short&>(l);
}

// FFMA2 helpers (pointwise path)
__device__ __forceinline__ void unpack2(float& lo, float& hi, ull v) {
    asm("mov.b64 {%0, %1}, %2;" : "=f"(lo), "=f"(hi) : "l"(v));
}
__device__ __forceinline__ ull fma2(ull a, ull b, ull c) {
    ull d;
    asm("fma.rn.f32x2 %0, %1, %2, %3;" : "=l"(d) : "l"(a), "l"(b), "l"(c));
    return d;
}

// ======================= prep kernels ======================================
__global__ void xpack_k(const float* __restrict__ x) {
    int i = blockIdx.x * blockDim.x + threadIdx.x;
    if (i >= BB * CC * HW) return;
    unsigned short hu, lu;
    bf_split(x[i], hu, lu);
    g_xpk[i] = (uint32_t)hu | ((uint32_t)lu << 16);
}

// [t][mh][split][m][k] <- offset_w[mg][cin][s];  t=(s*4+kc), cin=kc*32+k
__global__ void wprep_offbf(const float* __restrict__ ow) {
    int idx = blockIdx.x * blockDim.x + threadIdx.x;
    if (idx >= NSTG * 2 * 2 * 128 * 32) return;
    int kk = idx & 31;
    int m  = (idx >> 5) & 127;
    int split = (idx >> 12) & 1;
    int mh = (idx >> 13) & 1;
    int t  = idx >> 14;
    int cin = (t & 3) * 32 + kk;
    int s   = t >> 2;
    int mg  = mh * 128 + m;
    float v = ow[mg * 1152 + cin * 9 + s];
    unsigned short hu, lu;
    bf_split(v, hu, lu);
    g_Aoffbf[idx] = split ? lu : hu;
}

__global__ void wprep_pw(const float* __restrict__ pw) {
    int idx = blockIdx.x * blockDim.x + threadIdx.x;
    if (idx >= 128 * 256) return;
    int m = idx & 255;
    int k = idx >> 8;
    float v = pw[m * 128 + k];
    g_Adup_pw[(size_t)k * 512 + 2 * m]     = v;
    g_Adup_pw[(size_t)k * 512 + 2 * m + 1] = v;
}

// ======================= offset conv: bf16-split mma ======================
// CTA: M=128 (mhalf of 256) x N=128 pixels, K=1152 over 36 stages of 32.
// smem: A [2buf][2split][128 rows x 80B] = 40960
//       B [2buf][2split][32 rows x 272B] = 34816
#define SA_BUF   20480
#define SA_SPL   10240
#define SB_BASE  40960
#define SB_BUF   17408
#define SB_SPL   8704
#define OFFC_SMEM 75776

__global__ __launch_bounds__(256, 1)
void offconv_mma(const unsigned short* __restrict__ Abf,
                 const uint32_t* __restrict__ xpk,
                 const float* __restrict__ bias,
                 float* __restrict__ Odst)
{
    extern __shared__ char smem[];
    const uint32_t sA = smem_u32(smem);
    const uint32_t sB = sA + SB_BASE;

    const int tid  = threadIdx.x;
    const int lane = tid & 31;
    const int wid  = tid >> 5;
    const int mw   = wid & 1;      // 0..1
    const int nw   = wid >> 1;     // 0..3

    const int mhalf   = blockIdx.y;
    const int b       = blockIdx.x / 98;
    const int remBase = (blockIdx.x % 98) * 128;

    // ---- B-load geometry (per thread: 16 consecutive pixels of one k-row) --
    const int krow   = tid >> 3;          // 0..31
    const int pstart = (tid & 7) * 16;
    uint32_t mw0 = 0, mw1 = 0, mh0 = 0, mh1 = 0;
#pragma unroll
    for (int i = 0; i < 16; i++) {
        int rem = remBase + pstart + i;
        int h = rem / WW, w = rem - h * WW;
        if (w == 0)       mw0 |= 1u << i;
        if (w == WW - 1)  mw1 |= 1u << i;
        if (h == 0)       mh0 |= 1u << i;
        if (h == HH - 1)  mh1 |= 1u << i;
    }

    const int am     = tid & 127;
    const int asplit = tid >> 7;

    uint32_t v[16];

    auto cpA = [&](int t, int buf) {
        const unsigned short* src =
            Abf + (((size_t)(t * 2 + mhalf) * 2 + asplit) * 128 + am) * 32;
        uint32_t dst = sA + buf * SA_BUF + asplit * SA_SPL + am * 80;
        cp16(dst,      src);
        cp16(dst + 16, src + 8);
        cp16(dst + 32, src + 16);
        cp16(dst + 48, src + 24);
    };

    auto ldgB = [&](int t) {
        const int s  = t >> 2;
        const int dh = s / 3 - 1;
        const int dw = s % 3 - 1;
        const int cin = (t & 3) * 32 + krow;
        const uint32_t bad = (dw < 0 ? mw0 : (dw > 0 ? mw1 : 0u))
                           | (dh < 0 ? mh0 : (dh > 0 ? mh1 : 0u));
        const uint32_t* src = xpk + ((size_t)b * CC + cin) * HW
                            + remBase + pstart + dh * WW + dw;
#pragma unroll
        for (int i = 0; i < 16; i++) {
            bool ok = ((bad >> i) & 1u) == 0u;
            v[i] = ok ? __ldg(src + i) : 0u;
        }
    };

    auto stsB = [&](int buf) {
        uint32_t ph[8], pl[8];
#pragma unroll
        for (int j = 0; j < 8; j++) {
            ph[j] = prmt(v[2 * j], v[2 * j + 1], 0x5410);
            pl[j] = prmt(v[2 * j], v[2 * j + 1], 0x7632);
        }
        uint32_t d0 = sB + buf * SB_BUF + krow * 272 + pstart * 2;
        sts128(d0,                 ph[0], ph[1], ph[2], ph[3]);
        sts128(d0 + 16,            ph[4], ph[5], ph[6], ph[7]);
        sts128(d0 + SB_SPL,        pl[0], pl[1], pl[2], pl[3]);
        sts128(d0 + SB_SPL + 16,   pl[4], pl[5], pl[6], pl[7]);
    };

    float acc[4][4][4];
#pragma unroll
    for (int mt = 0; mt < 4; mt++)
#pragma unroll
        for (int nt = 0; nt < 4; nt++)
#pragma unroll
            for (int r = 0; r < 4; r++) acc[mt][nt][r] = 0.f;

    const uint32_t aOff = (uint32_t)((mw * 64 + (lane & 15)) * 80 + (lane >> 4) * 16);
    const uint32_t bOff = (uint32_t)((lane & 15) * 272 + nw * 64);

    // ---- prologue ----
    cpA(0, 0);
    CP_COMMIT();
    ldgB(0);
    stsB(0);

    for (int t = 0; t < NSTG; t++) {
        const int buf = t & 1;
        CP_WAIT0();
        __syncthreads();      // A[t] + B[t] ready; all warps done with t-1

        if (t + 1 < NSTG) {
            ldgB(t + 1);
            cpA(t + 1, buf ^ 1);
            CP_COMMIT();
        }

        // ---- compute stage t ----
        const uint32_t aH = sA + buf * SA_BUF + aOff;
        const uint32_t aL = aH + SA_SPL;
        const uint32_t bH = sB + buf * SB_BUF + bOff;
        const uint32_t bL = bH + SB_SPL;
#pragma unroll
        for (int kh = 0; kh < 2; kh++) {
            uint32_t ah[4][4], al[4][4];
#pragma unroll
            for (int mt = 0; mt < 4; mt++) {
                ldsm_x4(ah[mt], aH + mt * 1280 + kh * 32);
                ldsm_x4(al[mt], aL + mt * 1280 + kh * 32);
            }
            uint32_t bh[4][2], bl[4][2];
#pragma unroll
            for (int nt = 0; nt < 4; nt++) {
                ldsm_x2t(bh[nt], bH + kh * 4352 + nt * 16);
                ldsm_x2t(bl[nt], bL + kh * 4352 + nt * 16);
            }
#pragma unroll
            for (int mt = 0; mt < 4; mt++)
#pragma unroll
                for (int nt = 0; nt < 4; nt++) {
                    mma_bf16(acc[mt][nt], ah[mt], bh[nt]);
                    mma_bf16(acc[mt][nt], ah[mt], bl[nt]);
                    mma_bf16(acc[mt][nt], al[mt], bh[nt]);
                }
        }

        if (t + 1 < NSTG) stsB(buf ^ 1);
    }

    // ---- epilogue: bias + tanh + store ----
    const int ml = lane >> 2;
    const int nl = 2 * (lane & 3);
#pragma unroll
    for (int mt = 0; mt < 4; mt++) {
        const int mg0 = mhalf * 128 + mw * 64 + mt * 16 + ml;
        const float b0 = bias[mg0];
        const float b1 = bias[mg0 + 8];
        float* r0 = Odst + ((size_t)b * MOFF + mg0) * HW + remBase + nw * 32 + nl;
        float* r1 = r0 + (size_t)8 * HW;
#pragma unroll
        for (int nt = 0; nt < 4; nt++) {
            float2 o0, o1;
            o0.x = tanhf(acc[mt][nt][0] + b0);
            o0.y = tanhf(acc[mt][nt][1] + b0);
            o1.x = tanhf(acc[mt][nt][2] + b1);
            o1.y = tanhf(acc[mt][nt][3] + b1);
            *reinterpret_cast<float2*>(r0 + nt * 8) = o0;
            *reinterpret_cast<float2*>(r1 + nt * 8) = o1;
        }
    }
}

// ======================= pointwise: FFMA2 GEMM (from R5) ===================
#define BKT 16
#define AS_FLOATS (BKT * 256)
#define BS_FLOATS (BKT * 128)

__global__ __launch_bounds__(256, 2)
void gemm_pw(const float* __restrict__ Adup,
             const float* __restrict__ Bsrc,
             float* __restrict__ Cdst)
{
    extern __shared__ float smemf[];
    float* As2 = smemf;
    float* Bsm = smemf + 2 * AS_FLOATS;
    const uint32_t sA = smem_u32(As2);
    const uint32_t sB = smem_u32(Bsm);

    const int tid  = threadIdx.x;
    const int tRow = tid >> 4;
    const int tCol = tid & 15;

    const int nBase   = blockIdx.x * 128;
    const int b_img   = nBase / HW;
    const int remBase = nBase % HW;
    const int mBase   = blockIdx.y * 128;

    const int aRow   = tid >> 4;
    const int aCol16 = (tid & 15) * 16;
    const int bRow   = tid >> 4;
    const int bCol   = (tid & 15) * 8;

    constexpr int K = 128;
    constexpr int NT = K / BKT;

    auto load_stage = [&](int t, int buf) {
        {
            const float* src = Adup + ((size_t)(t * BKT + aRow)) * 512
                             + mBase * 2 + aCol16;
            const uint32_t dst = sA + (buf * AS_FLOATS + aRow * 256 + aCol16) * 4;
            cp16(dst,      src);
            cp16(dst + 16, src + 4);
            cp16(dst + 32, src + 8);
            cp16(dst + 48, src + 12);
        }
        {
            const int k = t * BKT + bRow;
            const float* src = Bsrc + ((size_t)b_img * K + k) * HW + remBase + bCol;
            const uint32_t bdst = sB + (buf * BS_FLOATS + bRow * 128 + bCol) * 4;
            cp16(bdst,      src);
            cp16(bdst + 16, src + 4);
        }
    };

    ull acc2[8][4];
#pragma unroll
    for (int i = 0; i < 8; i++)
#pragma unroll
        for (int j = 0; j < 4; j++) acc2[i][j] = 0ull;

    load_stage(0, 0);
    CP_COMMIT();

    for (int t = 0; t < NT; t++) {
        const int buf = t & 1;
        if (t + 1 < NT) {
            load_stage(t + 1, buf ^ 1);
            CP_COMMIT();
            asm volatile("cp.async.wait_group 1;" ::: "memory");
        } else {
            CP_WAIT0();
        }
        __syncthreads();

        const float* abase = As2 + buf * AS_FLOATS + tRow * 16;
        const float* bbase = Bsm + buf * BS_FLOATS + tCol * 8;
#pragma unroll
        for (int kk = 0; kk < BKT; kk++) {
            ull regM2[8];
            {
                const ulonglong2* ap =
                    reinterpret_cast<const ulonglong2*>(abase + kk * 256);
                ulonglong2 q0 = ap[0], q1 = ap[1], q2 = ap[2], q3 = ap[3];
                regM2[0] = q0.x; regM2[1] = q0.y;
                regM2[2] = q1.x; regM2[3] = q1.y;
                regM2[4] = q2.x; regM2[5] = q2.y;
                regM2[6] = q3.x; regM2[7] = q3.y;
            }
            ull regN2[4];
            {
                const ulonglong2* bp =
                    reinterpret_cast<const ulonglong2*>(bbase + kk * 128);
                ulonglong2 n0 = bp[0], n1 = bp[1];
                regN2[0] = n0.x; regN2[1] = n0.y;
                regN2[2] = n1.x; regN2[3] = n1.y;
            }
#pragma unroll
            for (int i = 0; i < 8; i++)
#pragma unroll
                for (int j = 0; j < 4; j++)
                    acc2[i][j] = fma2(regM2[i], regN2[j], acc2[i][j]);
        }
        __syncthreads();
    }

#pragma unroll
    for (int i = 0; i < 8; i++) {
        const int m = mBase + tRow * 8 + i;
        float* cp = Cdst + ((size_t)b_img * 256 + m) * HW + remBase + tCol * 8;
        float out[8];
#pragma unroll
        for (int j = 0; j < 4; j++) {
            float lo, hi;
            unpack2(lo, hi, acc2[i][j]);
            out[2 * j] = lo; out[2 * j + 1] = hi;
        }
        *reinterpret_cast<float4*>(cp)     = make_float4(out[0], out[1], out[2], out[3]);
        *reinterpret_cast<float4*>(cp + 4) = make_float4(out[4], out[5], out[6], out[7]);
    }
}

// ======================= depthwise 3x3 =====================================
__global__ __launch_bounds__(256)
void depthwise_k(const float* __restrict__ x,
                 const float* __restrict__ wgt,
                 float* __restrict__ out)
{
    const int idx = blockIdx.x * blockDim.x + threadIdx.x;
    if (idx >= BB * CC * HW) return;
    const int rem = idx % HW;
    const int bc  = idx / HW;
    const int c   = bc % CC;
    const int h   = rem / WW;
    const int w   = rem - h * WW;

    const float* wp = wgt + c * 9;
    const float* xp = x + (size_t)bc * HW;

    float accv = 0.f;
#pragma unroll
    for (int kh = 0; kh < 3; kh++) {
        const int ih = h + kh - 1;
        if ((unsigned)ih >= (unsigned)HH) continue;
#pragma unroll
        for (int kw = 0; kw < 3; kw++) {
            const int iw = w + kw - 1;
            if ((unsigned)iw >= (unsigned)WW) continue;
            accv = fmaf(__ldg(xp + ih * WW + iw), __ldg(wp + kh * 3 + kw), accv);
        }
    }
    out[idx] = accv;
}

// ======================= grid sample =======================================
__global__ __launch_bounds__(256)
void gridsample_k(const float* __restrict__ off,
                  const float* __restrict__ src,
                  float* __restrict__ dst)
{
    const int idx = blockIdx.x * blockDim.x + threadIdx.x;
    if (idx >= BB * CC * HW) return;
    const int rem = idx % HW;
    const int bc  = idx / HW;
    const int b   = bc / CC;
    const int c   = bc % CC;
    const int h   = rem / WW;
    const int w   = rem - h * WW;

    const float gx = -1.f + 2.f * (float)w / (float)(WW - 1);
    const float gy = -1.f + 2.f * (float)h / (float)(HH - 1);

    const int jx = 2 * c;
    const int jy = 2 * c + 1;
    const float basex = (jx < CC) ? gx : gy;
    const float basey = (jy < CC) ? gx : gy;

    const float offx = __ldg(off + ((size_t)b * MOFF + jx) * HW + rem);
    const float offy = __ldg(off + ((size_t)b * MOFF + jy) * HW + rem);

    float sx = fminf(fmaxf(basex + offx, -1.f), 1.f);
    float sy = fminf(fmaxf(basey + offy, -1.f), 1.f);

    const float ix = (sx + 1.f) * ((float)WW * 0.5f) - 0.5f;
    const float iy = (sy + 1.f) * ((float)HH * 0.5f) - 0.5f;

    const float x0f = floorf(ix);
    const float y0f = floorf(iy);
    const float wx  = ix - x0f;
    const float wy  = iy - y0f;
    const int x0 = (int)x0f;
    const int y0 = (int)y0f;

    const float* ch = src + (size_t)bc * HW;

    auto gather = [&](int yi, int xi) -> float {
        if ((unsigned)yi < (unsigned)HH && (unsigned)xi < (unsigned)WW)
            return __ldg(ch + yi * WW + xi);
        return 0.f;
    };

    const float v00 = gather(y0,     x0);
    const float v01 = gather(y0,     x0 + 1);
    const float v10 = gather(y0 + 1, x0);
    const float v11 = gather(y0 + 1, x0 + 1);

    dst[idx] = v00 * (1.f - wx) * (1.f - wy)
             + v01 * wx         * (1.f - wy)
             + v10 * (1.f - wx) * wy
             + v11 * wx         * wy;
}

// ======================= launch ============================================
extern "C" void kernel_launch(void* const* d_in, const int* in_sizes, int n_in,
                              void* d_out, int out_size)
{
    const float* x        = (const float*)d_in[0];
    const float* depth_w  = (const float*)d_in[1];
    const float* point_w  = (const float*)d_in[2];
    const float* offset_w = (const float*)d_in[3];
    const float* offset_b = (const float*)d_in[4];
    float* out = (float*)d_out;

    float* offset_p; cudaGetSymbolAddress((void**)&offset_p, g_offset);
    float* dw_p;     cudaGetSymbolAddress((void**)&dw_p,     g_dw);
    float* samp_p;   cudaGetSymbolAddress((void**)&samp_p,   g_samp);
    uint32_t* xpk_p; cudaGetSymbolAddress((void**)&xpk_p,    g_xpk);
    unsigned short* abf_p; cudaGetSymbolAddress((void**)&abf_p, g_Aoffbf);
    float* adpw_p;   cudaGetSymbolAddress((void**)&adpw_p,   g_Adup_pw);

    cudaFuncSetAttribute(offconv_mma,
                         cudaFuncAttributeMaxDynamicSharedMemorySize, OFFC_SMEM);
    const int PW_SMEM = (2 * AS_FLOATS + 2 * BS_FLOATS) * 4;
    cudaFuncSetAttribute(gemm_pw,
                         cudaFuncAttributeMaxDynamicSharedMemorySize, PW_SMEM);

    // 0) prep
    xpack_k<<<(BB * CC * HW + 255) / 256, 256>>>(x);
    wprep_offbf<<<(NSTG * 2 * 2 * 128 * 32 + 255) / 256, 256>>>(offset_w);
    wprep_pw<<<(128 * 256 + 255) / 256, 256>>>(point_w);

    // 1) offset conv (bf16-split mma) + bias + tanh
    {
        dim3 g(98 * BB, 2);
        offconv_mma<<<g, 256, OFFC_SMEM>>>(abf_p, xpk_p, offset_b, offset_p);
    }

    // 2) depthwise
    {
        const int total = BB * CC * HW;
        depthwise_k<<<(total + 255) / 256, 256>>>(x, depth_w, dw_p);
    }

    // 3) grid sample
    {
        const int total = BB * CC * HW;
        gridsample_k<<<(total + 255) / 256, 256>>>(offset_p, dw_p, samp_p);
    }

    // 4) pointwise 1x1 -> out
    {
        dim3 g(BB * HW / 128, 2);
        gemm_pw<<<g, 256, PW_SMEM>>>(adpw_p, samp_p, out);
    }
}

// round 7
// speedup vs baseline: 1.9382x; 1.2466x over previous
#include <cuda_runtime.h>
#include <cuda_bf16.h>
#include <cstdint>
#include <math.h>

// ---------------------------------------------------------------------------
// CDConv: offset-conv(3x3,128->256, bf16-split mma.sync)+tanh -> depthwise ->
//         grid_sample(->bf16 hi/lo planes) -> pointwise(1x1, bf16-split mma)
// B=16, C=128, H=W=112, OUTC=256
// ---------------------------------------------------------------------------

#define BB   16
#define CC   128
#define HH   112
#define WW   112
#define HW   12544
#define MOFF 256
#define NSTG 36               // offset conv: K=1152 / 32
#define NSTG_PW 4             // pointwise:  K=128 / 32

__device__ float    g_offset[BB * MOFF * HW];
__device__ float    g_dw[BB * CC * HW];
__device__ uint32_t g_xpk[BB * CC * HW];                     // {bf16 hi | lo<<16}
__device__ unsigned short g_shi[BB * CC * HW];               // sampled hi plane
__device__ unsigned short g_slo[BB * CC * HW];               // sampled lo plane
__device__ unsigned short g_Aoffbf[NSTG * 2 * 2 * 128 * 32]; // [t][mh][split][m][k]
__device__ unsigned short g_Apwbf[NSTG_PW * 2 * 2 * 128 * 32];

// ======================= helpers ==========================================
__device__ __forceinline__ uint32_t smem_u32(const void* p) {
    uint32_t a;
    asm("{ .reg .u64 t; cvta.to.shared.u64 t, %1; cvt.u32.u64 %0, t; }"
        : "=r"(a) : "l"(p));
    return a;
}
__device__ __forceinline__ void cp16(uint32_t dst, const void* src) {
    asm volatile("cp.async.cg.shared.global [%0], [%1], 16;"
                 :: "r"(dst), "l"(src) : "memory");
}
#define CP_COMMIT() asm volatile("cp.async.commit_group;" ::: "memory")
#define CP_WAIT0()  asm volatile("cp.async.wait_group 0;" ::: "memory")

__device__ __forceinline__ uint32_t prmt(uint32_t a, uint32_t b, uint32_t sel) {
    uint32_t d;
    asm("prmt.b32 %0, %1, %2, %3;" : "=r"(d) : "r"(a), "r"(b), "r"(sel));
    return d;
}
__device__ __forceinline__ void sts128(uint32_t a, uint32_t x, uint32_t y,
                                       uint32_t z, uint32_t w) {
    asm volatile("st.shared.v4.b32 [%0], {%1,%2,%3,%4};"
                 :: "r"(a), "r"(x), "r"(y), "r"(z), "r"(w) : "memory");
}
__device__ __forceinline__ void ldsm_x4(uint32_t* r, uint32_t addr) {
    asm volatile("ldmatrix.sync.aligned.m8n8.x4.shared.b16 {%0,%1,%2,%3}, [%4];"
                 : "=r"(r[0]), "=r"(r[1]), "=r"(r[2]), "=r"(r[3]) : "r"(addr));
}
__device__ __forceinline__ void ldsm_x2t(uint32_t* r, uint32_t addr) {
    asm volatile("ldmatrix.sync.aligned.m8n8.x2.trans.shared.b16 {%0,%1}, [%2];"
                 : "=r"(r[0]), "=r"(r[1]) : "r"(addr));
}
__device__ __forceinline__ void mma_bf16(float* c, const uint32_t* a, const uint32_t* b) {
    asm volatile(
        "mma.sync.aligned.m16n8k16.row.col.f32.bf16.bf16.f32 "
        "{%0,%1,%2,%3}, {%4,%5,%6,%7}, {%8,%9}, {%0,%1,%2,%3};"
        : "+f"(c[0]), "+f"(c[1]), "+f"(c[2]), "+f"(c[3])
        : "r"(a[0]), "r"(a[1]), "r"(a[2]), "r"(a[3]), "r"(b[0]), "r"(b[1]));
}

__device__ __forceinline__ void bf_split(float v, unsigned short& hu, unsigned short& lu) {
    __nv_bfloat16 h = __float2bfloat16(v);
    float hf = __bfloat162float(h);
    __nv_bfloat16 l = __float2bfloat16(v - hf);
    hu = reinterpret_cast<unsigned short&>(h);
    lu = reinterpret_cast<unsigned short&>(l);
}

// ======================= prep kernels ======================================
__global__ void xpack_k(const float* __restrict__ x) {
    int i = blockIdx.x * blockDim.x + threadIdx.x;
    if (i >= BB * CC * HW) return;
    unsigned short hu, lu;
    bf_split(x[i], hu, lu);
    g_xpk[i] = (uint32_t)hu | ((uint32_t)lu << 16);
}

// [t][mh][split][m][k] <- offset_w[mg][cin][s];  t=(s*4+kc), cin=kc*32+k
__global__ void wprep_offbf(const float* __restrict__ ow) {
    int idx = blockIdx.x * blockDim.x + threadIdx.x;
    if (idx >= NSTG * 2 * 2 * 128 * 32) return;
    int kk = idx & 31;
    int m  = (idx >> 5) & 127;
    int split = (idx >> 12) & 1;
    int mh = (idx >> 13) & 1;
    int t  = idx >> 14;
    int cin = (t & 3) * 32 + kk;
    int s   = t >> 2;
    int mg  = mh * 128 + m;
    float v = ow[mg * 1152 + cin * 9 + s];
    unsigned short hu, lu;
    bf_split(v, hu, lu);
    g_Aoffbf[idx] = split ? lu : hu;
}

__global__ void wprep_pwbf(const float* __restrict__ pw) {
    int idx = blockIdx.x * blockDim.x + threadIdx.x;
    if (idx >= NSTG_PW * 2 * 2 * 128 * 32) return;
    int kk = idx & 31;
    int m  = (idx >> 5) & 127;
    int split = (idx >> 12) & 1;
    int mh = (idx >> 13) & 1;
    int t  = idx >> 14;
    int cin = t * 32 + kk;
    int mg  = mh * 128 + m;
    float v = pw[mg * 128 + cin];
    unsigned short hu, lu;
    bf_split(v, hu, lu);
    g_Apwbf[idx] = split ? lu : hu;
}

// ======================= shared tile geometry ==============================
// A smem: [2buf][2split][128 rows x 80B]; B smem: [2buf][2split][32 rows x 272B]
#define SA_BUF   20480
#define SA_SPL   10240
#define SB_BASE  40960
#define SB_BUF   17408
#define SB_SPL   8704
#define TILE_SMEM 75776

// ======================= offset conv: bf16-split mma ======================
__global__ __launch_bounds__(256, 2)
void offconv_mma(const unsigned short* __restrict__ Abf,
                 const uint32_t* __restrict__ xpk,
                 const float* __restrict__ bias,
                 float* __restrict__ Odst)
{
    extern __shared__ char smem[];
    const uint32_t sA = smem_u32(smem);
    const uint32_t sB = sA + SB_BASE;

    const int tid  = threadIdx.x;
    const int lane = tid & 31;
    const int wid  = tid >> 5;
    const int mw   = wid & 1;
    const int nw   = wid >> 1;

    const int mhalf   = blockIdx.y;
    const int b       = blockIdx.x / 98;
    const int remBase = (blockIdx.x % 98) * 128;

    const int krow   = tid >> 3;          // 0..31
    const int pstart = (tid & 7) * 16;
    uint32_t mw0 = 0, mw1 = 0, mh0 = 0, mh1 = 0;
#pragma unroll
    for (int i = 0; i < 16; i++) {
        int rem = remBase + pstart + i;
        int h = rem / WW, w = rem - h * WW;
        if (w == 0)       mw0 |= 1u << i;
        if (w == WW - 1)  mw1 |= 1u << i;
        if (h == 0)       mh0 |= 1u << i;
        if (h == HH - 1)  mh1 |= 1u << i;
    }

    const int am     = tid & 127;
    const int asplit = tid >> 7;

    uint32_t v[16];

    auto cpA = [&](int t, int buf) {
        const unsigned short* src =
            Abf + (((size_t)(t * 2 + mhalf) * 2 + asplit) * 128 + am) * 32;
        uint32_t dst = sA + buf * SA_BUF + asplit * SA_SPL + am * 80;
        cp16(dst,      src);
        cp16(dst + 16, src + 8);
        cp16(dst + 32, src + 16);
        cp16(dst + 48, src + 24);
    };

    auto ldgB = [&](int t) {
        const int s  = t >> 2;
        const int dh = s / 3 - 1;
        const int dw = s % 3 - 1;
        const int cin = (t & 3) * 32 + krow;
        const uint32_t bad = (dw < 0 ? mw0 : (dw > 0 ? mw1 : 0u))
                           | (dh < 0 ? mh0 : (dh > 0 ? mh1 : 0u));
        const uint32_t* src = xpk + ((size_t)b * CC + cin) * HW
                            + remBase + pstart + dh * WW + dw;
#pragma unroll
        for (int i = 0; i < 16; i++) {
            bool ok = ((bad >> i) & 1u) == 0u;
            v[i] = ok ? __ldg(src + i) : 0u;
        }
    };

    auto stsB = [&](int buf) {
        uint32_t ph[8], pl[8];
#pragma unroll
        for (int j = 0; j < 8; j++) {
            ph[j] = prmt(v[2 * j], v[2 * j + 1], 0x5410);
            pl[j] = prmt(v[2 * j], v[2 * j + 1], 0x7632);
        }
        uint32_t d0 = sB + buf * SB_BUF + krow * 272 + pstart * 2;
        sts128(d0,               ph[0], ph[1], ph[2], ph[3]);
        sts128(d0 + 16,          ph[4], ph[5], ph[6], ph[7]);
        sts128(d0 + SB_SPL,      pl[0], pl[1], pl[2], pl[3]);
        sts128(d0 + SB_SPL + 16, pl[4], pl[5], pl[6], pl[7]);
    };

    float acc[4][4][4];
#pragma unroll
    for (int mt = 0; mt < 4; mt++)
#pragma unroll
        for (int nt = 0; nt < 4; nt++)
#pragma unroll
            for (int r = 0; r < 4; r++) acc[mt][nt][r] = 0.f;

    const uint32_t aOff = (uint32_t)((mw * 64 + (lane & 15)) * 80 + (lane >> 4) * 16);
    const uint32_t bOff = (uint32_t)((lane & 15) * 272 + nw * 64);

    cpA(0, 0);
    CP_COMMIT();
    ldgB(0);
    stsB(0);

    for (int t = 0; t < NSTG; t++) {
        const int buf = t & 1;
        CP_WAIT0();
        __syncthreads();

        if (t + 1 < NSTG) {
            ldgB(t + 1);
            cpA(t + 1, buf ^ 1);
            CP_COMMIT();
        }

        const uint32_t aH = sA + buf * SA_BUF + aOff;
        const uint32_t aL = aH + SA_SPL;
        const uint32_t bH = sB + buf * SB_BUF + bOff;
        const uint32_t bL = bH + SB_SPL;
#pragma unroll
        for (int kh = 0; kh < 2; kh++) {
            uint32_t bh[4][2], bl[4][2];
#pragma unroll
            for (int nt = 0; nt < 4; nt++) {
                ldsm_x2t(bh[nt], bH + kh * 4352 + nt * 16);
                ldsm_x2t(bl[nt], bL + kh * 4352 + nt * 16);
            }
#pragma unroll
            for (int mt = 0; mt < 4; mt++) {
                uint32_t ah[4], al[4];
                ldsm_x4(ah, aH + mt * 1280 + kh * 32);
                ldsm_x4(al, aL + mt * 1280 + kh * 32);
#pragma unroll
                for (int nt = 0; nt < 4; nt++) {
                    mma_bf16(acc[mt][nt], ah, bh[nt]);
                    mma_bf16(acc[mt][nt], ah, bl[nt]);
                    mma_bf16(acc[mt][nt], al, bh[nt]);
                }
            }
        }

        if (t + 1 < NSTG) stsB(buf ^ 1);
    }

    // epilogue: bias + tanh + store
    const int ml = lane >> 2;
    const int nl = 2 * (lane & 3);
#pragma unroll
    for (int mt = 0; mt < 4; mt++) {
        const int mg0 = mhalf * 128 + mw * 64 + mt * 16 + ml;
        const float b0 = bias[mg0];
        const float b1 = bias[mg0 + 8];
        float* r0 = Odst + ((size_t)b * MOFF + mg0) * HW + remBase + nw * 32 + nl;
        float* r1 = r0 + (size_t)8 * HW;
#pragma unroll
        for (int nt = 0; nt < 4; nt++) {
            float2 o0, o1;
            o0.x = tanhf(acc[mt][nt][0] + b0);
            o0.y = tanhf(acc[mt][nt][1] + b0);
            o1.x = tanhf(acc[mt][nt][2] + b1);
            o1.y = tanhf(acc[mt][nt][3] + b1);
            *reinterpret_cast<float2*>(r0 + nt * 8) = o0;
            *reinterpret_cast<float2*>(r1 + nt * 8) = o1;
        }
    }
}

// ======================= pointwise conv: bf16-split mma ====================
// Same tile geometry; B operand comes pre-split (hi/lo planes) -> pure cp.async.
__global__ __launch_bounds__(256, 2)
void pwconv_mma(const unsigned short* __restrict__ Abf,
                const unsigned short* __restrict__ shi,
                const unsigned short* __restrict__ slo,
                float* __restrict__ Cdst)
{
    extern __shared__ char smem[];
    const uint32_t sA = smem_u32(smem);
    const uint32_t sB = sA + SB_BASE;

    const int tid  = threadIdx.x;
    const int lane = tid & 31;
    const int wid  = tid >> 5;
    const int mw   = wid & 1;
    const int nw   = wid >> 1;

    const int mhalf   = blockIdx.y;
    const int b       = blockIdx.x / 98;
    const int remBase = (blockIdx.x % 98) * 128;

    const int krow   = tid >> 3;
    const int pstart = (tid & 7) * 16;

    const int am     = tid & 127;
    const int asplit = tid >> 7;

    auto load_stage = [&](int t, int buf) {
        {
            const unsigned short* src =
                Abf + (((size_t)(t * 2 + mhalf) * 2 + asplit) * 128 + am) * 32;
            uint32_t dst = sA + buf * SA_BUF + asplit * SA_SPL + am * 80;
            cp16(dst,      src);
            cp16(dst + 16, src + 8);
            cp16(dst + 32, src + 16);
            cp16(dst + 48, src + 24);
        }
        {
            const int cin = t * 32 + krow;
            const size_t so = ((size_t)b * CC + cin) * HW + remBase + pstart;
            uint32_t d0 = sB + buf * SB_BUF + krow * 272 + pstart * 2;
            cp16(d0,               shi + so);
            cp16(d0 + 16,          shi + so + 8);
            cp16(d0 + SB_SPL,      slo + so);
            cp16(d0 + SB_SPL + 16, slo + so + 8);
        }
    };

    float acc[4][4][4];
#pragma unroll
    for (int mt = 0; mt < 4; mt++)
#pragma unroll
        for (int nt = 0; nt < 4; nt++)
#pragma unroll
            for (int r = 0; r < 4; r++) acc[mt][nt][r] = 0.f;

    const uint32_t aOff = (uint32_t)((mw * 64 + (lane & 15)) * 80 + (lane >> 4) * 16);
    const uint32_t bOff = (uint32_t)((lane & 15) * 272 + nw * 64);

    load_stage(0, 0);
    CP_COMMIT();

    for (int t = 0; t < NSTG_PW; t++) {
        const int buf = t & 1;
        if (t + 1 < NSTG_PW) {
            load_stage(t + 1, buf ^ 1);
            CP_COMMIT();
            asm volatile("cp.async.wait_group 1;" ::: "memory");
        } else {
            CP_WAIT0();
        }
        __syncthreads();

        const uint32_t aH = sA + buf * SA_BUF + aOff;
        const uint32_t aL = aH + SA_SPL;
        const uint32_t bH = sB + buf * SB_BUF + bOff;
        const uint32_t bL = bH + SB_SPL;
#pragma unroll
        for (int kh = 0; kh < 2; kh++) {
            uint32_t bh[4][2], bl[4][2];
#pragma unroll
            for (int nt = 0; nt < 4; nt++) {
                ldsm_x2t(bh[nt], bH + kh * 4352 + nt * 16);
                ldsm_x2t(bl[nt], bL + kh * 4352 + nt * 16);
            }
#pragma unroll
            for (int mt = 0; mt < 4; mt++) {
                uint32_t ah[4], al[4];
                ldsm_x4(ah, aH + mt * 1280 + kh * 32);
                ldsm_x4(al, aL + mt * 1280 + kh * 32);
#pragma unroll
                for (int nt = 0; nt < 4; nt++) {
                    mma_bf16(acc[mt][nt], ah, bh[nt]);
                    mma_bf16(acc[mt][nt], ah, bl[nt]);
                    mma_bf16(acc[mt][nt], al, bh[nt]);
                }
            }
        }
        __syncthreads();
    }

    const int ml = lane >> 2;
    const int nl = 2 * (lane & 3);
#pragma unroll
    for (int mt = 0; mt < 4; mt++) {
        const int mg0 = mhalf * 128 + mw * 64 + mt * 16 + ml;
        float* r0 = Cdst + ((size_t)b * 256 + mg0) * HW + remBase + nw * 32 + nl;
        float* r1 = r0 + (size_t)8 * HW;
#pragma unroll
        for (int nt = 0; nt < 4; nt++) {
            float2 o0, o1;
            o0.x = acc[mt][nt][0];
            o0.y = acc[mt][nt][1];
            o1.x = acc[mt][nt][2];
            o1.y = acc[mt][nt][3];
            *reinterpret_cast<float2*>(r0 + nt * 8) = o0;
            *reinterpret_cast<float2*>(r1 + nt * 8) = o1;
        }
    }
}

// ======================= depthwise 3x3 =====================================
__global__ __launch_bounds__(256)
void depthwise_k(const float* __restrict__ x,
                 const float* __restrict__ wgt,
                 float* __restrict__ out)
{
    const int idx = blockIdx.x * blockDim.x + threadIdx.x;
    if (idx >= BB * CC * HW) return;
    const int rem = idx % HW;
    const int bc  = idx / HW;
    const int c   = bc % CC;
    const int h   = rem / WW;
    const int w   = rem - h * WW;

    const float* wp = wgt + c * 9;
    const float* xp = x + (size_t)bc * HW;

    float accv = 0.f;
#pragma unroll
    for (int kh = 0; kh < 3; kh++) {
        const int ih = h + kh - 1;
        if ((unsigned)ih >= (unsigned)HH) continue;
#pragma unroll
        for (int kw = 0; kw < 3; kw++) {
            const int iw = w + kw - 1;
            if ((unsigned)iw >= (unsigned)WW) continue;
            accv = fmaf(__ldg(xp + ih * WW + iw), __ldg(wp + kh * 3 + kw), accv);
        }
    }
    out[idx] = accv;
}

// ======================= grid sample -> split bf16 planes ==================
__global__ __launch_bounds__(256)
void gridsample_k(const float* __restrict__ off,
                  const float* __restrict__ src,
                  unsigned short* __restrict__ dhi,
                  unsigned short* __restrict__ dlo)
{
    const int idx = blockIdx.x * blockDim.x + threadIdx.x;
    if (idx >= BB * CC * HW) return;
    const int rem = idx % HW;
    const int bc  = idx / HW;
    const int b   = bc / CC;
    const int c   = bc % CC;
    const int h   = rem / WW;
    const int w   = rem - h * WW;

    const float gx = -1.f + 2.f * (float)w / (float)(WW - 1);
    const float gy = -1.f + 2.f * (float)h / (float)(HH - 1);

    const int jx = 2 * c;
    const int jy = 2 * c + 1;
    const float basex = (jx < CC) ? gx : gy;
    const float basey = (jy < CC) ? gx : gy;

    const float offx = __ldg(off + ((size_t)b * MOFF + jx) * HW + rem);
    const float offy = __ldg(off + ((size_t)b * MOFF + jy) * HW + rem);

    float sx = fminf(fmaxf(basex + offx, -1.f), 1.f);
    float sy = fminf(fmaxf(basey + offy, -1.f), 1.f);

    const float ix = (sx + 1.f) * ((float)WW * 0.5f) - 0.5f;
    const float iy = (sy + 1.f) * ((float)HH * 0.5f) - 0.5f;

    const float x0f = floorf(ix);
    const float y0f = floorf(iy);
    const float wx  = ix - x0f;
    const float wy  = iy - y0f;
    const int x0 = (int)x0f;
    const int y0 = (int)y0f;

    const float* ch = src + (size_t)bc * HW;

    auto gather = [&](int yi, int xi) -> float {
        if ((unsigned)yi < (unsigned)HH && (unsigned)xi < (unsigned)WW)
            return __ldg(ch + yi * WW + xi);
        return 0.f;
    };

    const float v00 = gather(y0,     x0);
    const float v01 = gather(y0,     x0 + 1);
    const float v10 = gather(y0 + 1, x0);
    const float v11 = gather(y0 + 1, x0 + 1);

    float r = v00 * (1.f - wx) * (1.f - wy)
            + v01 * wx         * (1.f - wy)
            + v10 * (1.f - wx) * wy
            + v11 * wx         * wy;

    unsigned short hu, lu;
    bf_split(r, hu, lu);
    dhi[idx] = hu;
    dlo[idx] = lu;
}

// ======================= launch ============================================
extern "C" void kernel_launch(void* const* d_in, const int* in_sizes, int n_in,
                              void* d_out, int out_size)
{
    const float* x        = (const float*)d_in[0];
    const float* depth_w  = (const float*)d_in[1];
    const float* point_w  = (const float*)d_in[2];
    const float* offset_w = (const float*)d_in[3];
    const float* offset_b = (const float*)d_in[4];
    float* out = (float*)d_out;

    float* offset_p; cudaGetSymbolAddress((void**)&offset_p, g_offset);
    float* dw_p;     cudaGetSymbolAddress((void**)&dw_p,     g_dw);
    uint32_t* xpk_p; cudaGetSymbolAddress((void**)&xpk_p,    g_xpk);
    unsigned short* shi_p; cudaGetSymbolAddress((void**)&shi_p, g_shi);
    unsigned short* slo_p; cudaGetSymbolAddress((void**)&slo_p, g_slo);
    unsigned short* aoff_p; cudaGetSymbolAddress((void**)&aoff_p, g_Aoffbf);
    unsigned short* apw_p;  cudaGetSymbolAddress((void**)&apw_p,  g_Apwbf);

    cudaFuncSetAttribute(offconv_mma,
                         cudaFuncAttributeMaxDynamicSharedMemorySize, TILE_SMEM);
    cudaFuncSetAttribute(pwconv_mma,
                         cudaFuncAttributeMaxDynamicSharedMemorySize, TILE_SMEM);

    // 0) prep
    xpack_k<<<(BB * CC * HW + 255) / 256, 256>>>(x);
    wprep_offbf<<<(NSTG * 2 * 2 * 128 * 32 + 255) / 256, 256>>>(offset_w);
    wprep_pwbf<<<(NSTG_PW * 2 * 2 * 128 * 32 + 255) / 256, 256>>>(point_w);

    // 1) offset conv + bias + tanh
    {
        dim3 g(98 * BB, 2);
        offconv_mma<<<g, 256, TILE_SMEM>>>(aoff_p, xpk_p, offset_b, offset_p);
    }

    // 2) depthwise
    {
        const int total = BB * CC * HW;
        depthwise_k<<<(total + 255) / 256, 256>>>(x, depth_w, dw_p);
    }

    // 3) grid sample -> split planes
    {
        const int total = BB * CC * HW;
        gridsample_k<<<(total + 255) / 256, 256>>>(offset_p, dw_p, shi_p, slo_p);
    }

    // 4) pointwise 1x1 (bf16-split mma) -> out
    {
        dim3 g(98 * BB, 2);
        pwconv_mma<<<g, 256, TILE_SMEM>>>(apw_p, shi_p, slo_p, out);
    }
}